// round 1
// baseline (speedup 1.0000x reference)
#include <cuda_runtime.h>
#include <math.h>

// Problem constants (from reference: BINSIZE=200, WIDTH=100000, BINWIDTH=500)
#define BINSIZE      200
#define BINWIDTH     500          // bins per region
#define N_CLUSTERS   20
#define N_ROI_MAX    200

// Precomputed log-density table: [n_regions_oi, n_clusters, BINWIDTH]
__device__ float g_heights[N_ROI_MAX * N_CLUSTERS * BINWIDTH];

// ---------------------------------------------------------------------------
// Kernel 1: build heights table.
// One block per (roi, cluster) row; 512 threads, 500 active bins.
// heights = (x - logsumexp(x)) - log(BINSIZE)
// ---------------------------------------------------------------------------
__global__ void __launch_bounds__(512) build_heights_kernel(
    const float* __restrict__ baseline,      // [n_regions, 500]
    const float* __restrict__ delta,         // [n_regions, 20, 500]
    const int*   __restrict__ regions_oi,    // [n_roi]
    int n_clusters)
{
    const int row = blockIdx.x;              // roi * n_clusters + cluster
    const int roi = row / n_clusters;
    const int cl  = row - roi * n_clusters;
    const int region = regions_oi[roi];

    const int b = threadIdx.x;
    float val = 0.0f;
    float v   = -INFINITY;
    if (b < BINWIDTH) {
        val = baseline[region * BINWIDTH + b]
            + delta[((long long)region * n_clusters + cl) * BINWIDTH + b];
        v = val;
    }

    __shared__ float red[16];
    __shared__ float s_bcast;

    // --- block max ---
    #pragma unroll
    for (int o = 16; o > 0; o >>= 1)
        v = fmaxf(v, __shfl_xor_sync(0xffffffffu, v, o));
    if ((threadIdx.x & 31) == 0) red[threadIdx.x >> 5] = v;
    __syncthreads();
    if (threadIdx.x < 32) {
        float x = (threadIdx.x < 16) ? red[threadIdx.x] : -INFINITY;
        #pragma unroll
        for (int o = 8; o > 0; o >>= 1)
            x = fmaxf(x, __shfl_xor_sync(0xffffffffu, x, o));
        if (threadIdx.x == 0) s_bcast = x;
    }
    __syncthreads();
    const float m = s_bcast;

    // --- block sum of exp(val - m) ---
    float e = (b < BINWIDTH) ? expf(val - m) : 0.0f;
    float s = e;
    #pragma unroll
    for (int o = 16; o > 0; o >>= 1)
        s += __shfl_xor_sync(0xffffffffu, s, o);
    if ((threadIdx.x & 31) == 0) red[threadIdx.x >> 5] = s;
    __syncthreads();
    if (threadIdx.x < 32) {
        float x = (threadIdx.x < 16) ? red[threadIdx.x] : 0.0f;
        #pragma unroll
        for (int o = 8; o > 0; o >>= 1)
            x += __shfl_xor_sync(0xffffffffu, x, o);
        if (threadIdx.x == 0) s_bcast = x;
    }
    __syncthreads();
    const float logz = m + logf(s_bcast);

    if (b < BINWIDTH) {
        // log_softmax - log(BINSIZE)
        g_heights[row * BINWIDTH + b] = val - logz - logf((float)BINSIZE);
    }
}

// ---------------------------------------------------------------------------
// Kernel 2: per-fragment gather, 4 fragments per thread (vectorized loads).
// ---------------------------------------------------------------------------
__global__ void __launch_bounds__(256) gather_kernel(
    const int*   __restrict__ coords,      // [n, 2]
    const int*   __restrict__ lrix,        // [n]
    const int*   __restrict__ lcix,        // [n]
    const int*   __restrict__ labels,      // [n_cells]
    const float* __restrict__ inside,      // [1]
    float*       __restrict__ out,         // [n, 2]
    int n)
{
    const int tid = blockIdx.x * blockDim.x + threadIdx.x;
    const int i0  = tid * 4;
    if (i0 >= n) return;

    // inside/outside logprob constants (uniform across all threads)
    const float x    = inside[0];
    const float l1p  = log1pf(expf(-x));         // -log(sigmoid(x)) = log1p(e^-x)
    const float lpIn  = -l1p     - logf((float)BINWIDTH);               // log(s)   - log(500)
    const float lpOut = -x - l1p - logf((float)(100000 - BINWIDTH));    // log(1-s) - log(99500)

    if (i0 + 4 <= n) {
        const int4 c01 = ((const int4*)coords)[tid * 2 + 0];  // frag0: (x,y) frag1: (z,w)
        const int4 c23 = ((const int4*)coords)[tid * 2 + 1];
        const int4 rr  = ((const int4*)lrix)[tid];
        const int4 cc  = ((const int4*)lcix)[tid];

        const int lab0 = labels[cc.x];
        const int lab1 = labels[cc.y];
        const int lab2 = labels[cc.z];
        const int lab3 = labels[cc.w];

        const int bl0 = c01.x / BINSIZE, br0 = c01.y / BINSIZE;
        const int bl1 = c01.z / BINSIZE, br1 = c01.w / BINSIZE;
        const int bl2 = c23.x / BINSIZE, br2 = c23.y / BINSIZE;
        const int bl3 = c23.z / BINSIZE, br3 = c23.w / BINSIZE;

        const float L0 = g_heights[(rr.x * N_CLUSTERS + lab0) * BINWIDTH + bl0];
        const float L1 = g_heights[(rr.y * N_CLUSTERS + lab1) * BINWIDTH + bl1];
        const float L2 = g_heights[(rr.z * N_CLUSTERS + lab2) * BINWIDTH + bl2];
        const float L3 = g_heights[(rr.w * N_CLUSTERS + lab3) * BINWIDTH + bl3];

        float4 o01, o23;
        o01.x = L0; o01.y = (bl0 == br0) ? lpIn : lpOut;
        o01.z = L1; o01.w = (bl1 == br1) ? lpIn : lpOut;
        o23.x = L2; o23.y = (bl2 == br2) ? lpIn : lpOut;
        o23.z = L3; o23.w = (bl3 == br3) ? lpIn : lpOut;
        ((float4*)out)[tid * 2 + 0] = o01;
        ((float4*)out)[tid * 2 + 1] = o23;
    } else {
        for (int i = i0; i < n; i++) {
            const int cx = coords[i * 2 + 0];
            const int cy = coords[i * 2 + 1];
            const int bl = cx / BINSIZE, br = cy / BINSIZE;
            const int lab = labels[lcix[i]];
            const int r = lrix[i];
            out[i * 2 + 0] = g_heights[(r * N_CLUSTERS + lab) * BINWIDTH + bl];
            out[i * 2 + 1] = (bl == br) ? lpIn : lpOut;
        }
    }
}

// ---------------------------------------------------------------------------
// Launch
// Inputs (metadata order):
//  0 baseline_weight   f32 [n_regions, 500]
//  1 delta_logit_weight f32 [n_regions, 20, 500]
//  2 inside            f32 [1]
//  3 regions_oi        i32 [n_roi]
//  4 coordinates       i32 [n, 2]
//  5 local_region_ix   i32 [n]
//  6 local_cell_ix     i32 [n]
//  7 labels            i32 [n_cells]
// output: f32 [n, 2]
// ---------------------------------------------------------------------------
extern "C" void kernel_launch(void* const* d_in, const int* in_sizes, int n_in,
                              void* d_out, int out_size)
{
    const float* baseline = (const float*)d_in[0];
    const float* delta    = (const float*)d_in[1];
    const float* inside   = (const float*)d_in[2];
    const int*   regions  = (const int*)d_in[3];
    const int*   coords   = (const int*)d_in[4];
    const int*   lrix     = (const int*)d_in[5];
    const int*   lcix     = (const int*)d_in[6];
    const int*   labels   = (const int*)d_in[7];
    float*       out      = (float*)d_out;

    const int n_roi      = in_sizes[3];
    const int n          = in_sizes[5];
    const int n_regions  = in_sizes[0] / BINWIDTH;
    const int n_clusters = (n_regions > 0) ? (in_sizes[1] / (n_regions * BINWIDTH)) : N_CLUSTERS;

    // Kernel 1: one block per (roi, cluster)
    build_heights_kernel<<<n_roi * n_clusters, 512>>>(baseline, delta, regions, n_clusters);

    // Kernel 2: 4 fragments per thread
    const int threads = 256;
    const int work    = (n + 3) / 4;
    const int blocks  = (work + threads - 1) / threads;
    gather_kernel<<<blocks, threads>>>(coords, lrix, lcix, labels, inside, out, n);
}

// round 2
// speedup vs baseline: 1.3112x; 1.3112x over previous
#include <cuda_runtime.h>
#include <math.h>

#define BINSIZE      200
#define BINWIDTH     500
#define N_CLUSTERS   20
#define N_ROI_MAX    200
#define N_CELLS_MAX  100000

// Precomputed log-density table: [n_roi, n_clusters, BINWIDTH]
__device__ float g_heights[N_ROI_MAX * N_CLUSTERS * BINWIDTH];
// labels compacted to uint8 (fits in L1D: 100KB < 228KB)
__device__ unsigned char g_labels8[N_CELLS_MAX];

// ---------------------------------------------------------------------------
// Kernel 1 (fused): blocks [0, rowBlocks) build heights (one warp per
// (roi,cluster) row, float4 loads, warp-shuffle reductions only).
// Blocks [rowBlocks, rowBlocks+packBlocks) compact labels int32 -> uint8.
// ---------------------------------------------------------------------------
__global__ void __launch_bounds__(256) build_kernel(
    const float* __restrict__ baseline,      // [n_regions, 500]
    const float* __restrict__ delta,         // [n_regions, 20, 500]
    const int*   __restrict__ regions_oi,    // [n_roi]
    const int*   __restrict__ labels,        // [n_cells]
    int n_rows, int n_clusters, int rowBlocks, int n_cells)
{
    if ((int)blockIdx.x < rowBlocks) {
        const int warp = (int)blockIdx.x * 8 + ((int)threadIdx.x >> 5);
        if (warp >= n_rows) return;
        const int lane = threadIdx.x & 31;
        const int roi = warp / n_clusters;
        const int cl  = warp - roi * n_clusters;
        const int region = regions_oi[roi];

        const float4* __restrict__ b4 = (const float4*)(baseline + (long long)region * BINWIDTH);
        const float4* __restrict__ d4 = (const float4*)(delta + ((long long)region * n_clusters + cl) * BINWIDTH);

        // 500 floats = 125 float4; lane handles idx = lane, lane+32, lane+64, lane+96
        float4 v[4];
        float m = -INFINITY;
        #pragma unroll
        for (int it = 0; it < 4; it++) {
            const int idx = lane + it * 32;
            if (idx < 125) {
                float4 a = b4[idx];
                float4 d = d4[idx];
                v[it].x = a.x + d.x; v[it].y = a.y + d.y;
                v[it].z = a.z + d.z; v[it].w = a.w + d.w;
                m = fmaxf(m, fmaxf(fmaxf(v[it].x, v[it].y), fmaxf(v[it].z, v[it].w)));
            }
        }
        #pragma unroll
        for (int o = 16; o > 0; o >>= 1)
            m = fmaxf(m, __shfl_xor_sync(0xffffffffu, m, o));

        float s = 0.0f;
        #pragma unroll
        for (int it = 0; it < 4; it++) {
            const int idx = lane + it * 32;
            if (idx < 125) {
                s += __expf(v[it].x - m) + __expf(v[it].y - m)
                   + __expf(v[it].z - m) + __expf(v[it].w - m);
            }
        }
        #pragma unroll
        for (int o = 16; o > 0; o >>= 1)
            s += __shfl_xor_sync(0xffffffffu, s, o);

        const float sub = m + __logf(s) + logf((float)BINSIZE);

        float4* __restrict__ o4 = (float4*)(g_heights + (long long)warp * BINWIDTH);
        #pragma unroll
        for (int it = 0; it < 4; it++) {
            const int idx = lane + it * 32;
            if (idx < 125) {
                float4 h;
                h.x = v[it].x - sub; h.y = v[it].y - sub;
                h.z = v[it].z - sub; h.w = v[it].w - sub;
                o4[idx] = h;
            }
        }
    } else {
        // label compaction: 4 cells per thread
        const int b = (int)blockIdx.x - rowBlocks;
        const int t = b * 256 + (int)threadIdx.x;
        const int i0 = t * 4;
        if (i0 + 4 <= n_cells) {
            const int4 l = ((const int4*)labels)[t];
            uchar4 p;
            p.x = (unsigned char)l.x; p.y = (unsigned char)l.y;
            p.z = (unsigned char)l.z; p.w = (unsigned char)l.w;
            ((uchar4*)g_labels8)[t] = p;
        } else {
            for (int i = i0; i < n_cells; i++)
                g_labels8[i] = (unsigned char)labels[i];
        }
    }
}

// ---------------------------------------------------------------------------
// Kernel 2: per-fragment gather, 8 fragments per thread.
// ---------------------------------------------------------------------------
__global__ void __launch_bounds__(256) gather_kernel(
    const int*   __restrict__ coords,      // [n, 2]
    const int*   __restrict__ lrix,        // [n]
    const int*   __restrict__ lcix,        // [n]
    const float* __restrict__ inside,      // [1]
    float*       __restrict__ out,         // [n, 2]
    int n)
{
    const int tid = blockIdx.x * blockDim.x + threadIdx.x;
    const int i0  = tid * 8;
    if (i0 >= n) return;

    const float x    = inside[0];
    const float l1p  = log1pf(expf(-x));
    const float lpIn  = -l1p     - logf((float)BINWIDTH);
    const float lpOut = -x - l1p - logf((float)(100000 - BINWIDTH));

    if (i0 + 8 <= n) {
        // streaming loads (all independent -> high MLP)
        int4 c[4], rr[2], qq[2];
        #pragma unroll
        for (int k = 0; k < 4; k++) c[k] = ((const int4*)coords)[tid * 4 + k];
        #pragma unroll
        for (int k = 0; k < 2; k++) rr[k] = ((const int4*)lrix)[tid * 2 + k];
        #pragma unroll
        for (int k = 0; k < 2; k++) qq[k] = ((const int4*)lcix)[tid * 2 + k];

        // label gathers (L1-resident 100KB table)
        int lab[8];
        lab[0] = g_labels8[qq[0].x]; lab[1] = g_labels8[qq[0].y];
        lab[2] = g_labels8[qq[0].z]; lab[3] = g_labels8[qq[0].w];
        lab[4] = g_labels8[qq[1].x]; lab[5] = g_labels8[qq[1].y];
        lab[6] = g_labels8[qq[1].z]; lab[7] = g_labels8[qq[1].w];

        int bl[8], br[8], r[8];
        #pragma unroll
        for (int k = 0; k < 4; k++) {
            bl[2*k]   = c[k].x / BINSIZE; br[2*k]   = c[k].y / BINSIZE;
            bl[2*k+1] = c[k].z / BINSIZE; br[2*k+1] = c[k].w / BINSIZE;
        }
        r[0] = rr[0].x; r[1] = rr[0].y; r[2] = rr[0].z; r[3] = rr[0].w;
        r[4] = rr[1].x; r[5] = rr[1].y; r[6] = rr[1].z; r[7] = rr[1].w;

        // heights gathers (L2-resident 8MB table)
        float L[8];
        #pragma unroll
        for (int k = 0; k < 8; k++)
            L[k] = g_heights[(r[k] * N_CLUSTERS + lab[k]) * BINWIDTH + bl[k]];

        #pragma unroll
        for (int k = 0; k < 4; k++) {
            float4 o;
            o.x = L[2*k];   o.y = (bl[2*k]   == br[2*k])   ? lpIn : lpOut;
            o.z = L[2*k+1]; o.w = (bl[2*k+1] == br[2*k+1]) ? lpIn : lpOut;
            ((float4*)out)[tid * 4 + k] = o;
        }
    } else {
        for (int i = i0; i < n; i++) {
            const int cx = coords[i * 2 + 0];
            const int cy = coords[i * 2 + 1];
            const int bl = cx / BINSIZE, br = cy / BINSIZE;
            const int lab = g_labels8[lcix[i]];
            const int rg = lrix[i];
            out[i * 2 + 0] = g_heights[(rg * N_CLUSTERS + lab) * BINWIDTH + bl];
            out[i * 2 + 1] = (bl == br) ? lpIn : lpOut;
        }
    }
}

// ---------------------------------------------------------------------------
extern "C" void kernel_launch(void* const* d_in, const int* in_sizes, int n_in,
                              void* d_out, int out_size)
{
    const float* baseline = (const float*)d_in[0];
    const float* delta    = (const float*)d_in[1];
    const float* inside   = (const float*)d_in[2];
    const int*   regions  = (const int*)d_in[3];
    const int*   coords   = (const int*)d_in[4];
    const int*   lrix     = (const int*)d_in[5];
    const int*   lcix     = (const int*)d_in[6];
    const int*   labels   = (const int*)d_in[7];
    float*       out      = (float*)d_out;

    const int n_roi      = in_sizes[3];
    const int n          = in_sizes[5];
    const int n_cells    = in_sizes[7];
    const int n_regions  = in_sizes[0] / BINWIDTH;
    const int n_clusters = (n_regions > 0) ? (in_sizes[1] / (n_regions * BINWIDTH)) : N_CLUSTERS;

    const int n_rows    = n_roi * n_clusters;
    const int rowBlocks = (n_rows + 7) / 8;                 // 8 warps (rows) per block
    const int packBlocks = (n_cells + 1023) / 1024;         // 4 cells/thread, 256 thr
    build_kernel<<<rowBlocks + packBlocks, 256>>>(
        baseline, delta, regions, labels, n_rows, n_clusters, rowBlocks, n_cells);

    const int threads = 256;
    const int work    = (n + 7) / 8;
    const int blocks  = (work + threads - 1) / threads;
    gather_kernel<<<blocks, threads>>>(coords, lrix, lcix, inside, out, n);
}